// round 11
// baseline (speedup 1.0000x reference)
#include <cuda_runtime.h>
#include <math.h>

typedef unsigned long long u64;

#define NG 8
#define NT 2048
#define NH 2048
#define NE 8
#define CAP 320
#define NTOK (NG * NT)        // 16384
#define TPBK 64               // tokens per block
#define NBLK (NTOK / TPBK)    // 256
#define BPG (NBLK / NG)       // 32 blocks per group
#define THREADS 512
#define NITER 16              // H chunks of 128 floats
#define ROWB 528              // stage row bytes/token (16B-aligned; 4l+c banks -> conflict-free phases)
#define STAGEB (TPBK * ROWB)  // 33792 B per stage
#define NSTAGE 4
#define SMEM_W 65536
#define STAGE_OFF SMEM_W
#define MISC_OFF (STAGE_OFF + NSTAGE * STAGEB)
// misc: logits 64*9*4 + bias 8*4 + arg 64*4 = 2592; mbar 4*8 at aligned tail
#define MBAR_OFF ((MISC_OFF + 2592 + 15) & ~15)
#define SMEM_TOTAL (MBAR_OFF + NSTAGE * 8)

// scratch: argmax ids; per-group completion counters.
// g_cnt is tested modulo BPG -> never needs resetting across graph replays.
__device__ unsigned char g_expert_id[NTOK];
__device__ unsigned int  g_cnt[NG];

__device__ __forceinline__ void fma2(u64& acc, u64 a, u64 b) {
    asm("fma.rn.f32x2 %0, %1, %2, %0;" : "+l"(acc) : "l"(a), "l"(b));
}
__device__ __forceinline__ u64 add2(u64 a, u64 b) {
    u64 r; asm("add.rn.f32x2 %0, %1, %2;" : "=l"(r) : "l"(a), "l"(b));
    return r;
}
__device__ __forceinline__ u64 pack2(float lo, float hi) {
    u64 r; asm("mov.b64 %0, {%1, %2};" : "=l"(r) : "f"(lo), "f"(hi));
    return r;
}
__device__ __forceinline__ u64 dup2(float v) { return pack2(v, v); }
__device__ __forceinline__ void unpack2(u64 v, float& lo, float& hi) {
    asm("mov.b64 {%0, %1}, %2;" : "=f"(lo), "=f"(hi) : "l"(v));
}
__device__ __forceinline__ void mbar_init(unsigned mbar, unsigned count) {
    asm volatile("mbarrier.init.shared.b64 [%0], %1;" :: "r"(mbar), "r"(count)
                 : "memory");
}
__device__ __forceinline__ void mbar_expect_tx(unsigned mbar, unsigned bytes) {
    asm volatile("mbarrier.arrive.expect_tx.shared.b64 _, [%0], %1;"
                 :: "r"(mbar), "r"(bytes) : "memory");
}
__device__ __forceinline__ void bulk_cp(unsigned dst, const void* src,
                                        unsigned bytes, unsigned mbar) {
    asm volatile(
        "cp.async.bulk.shared::cluster.global.mbarrier::complete_tx::bytes "
        "[%0], [%1], %2, [%3];"
        :: "r"(dst), "l"(src), "r"(bytes), "r"(mbar) : "memory");
}
__device__ __forceinline__ void mbar_wait(unsigned mbar, unsigned parity) {
    asm volatile(
        "{\n\t"
        ".reg .pred P1;\n\t"
        "WAIT_LOOP_%=:\n\t"
        "mbarrier.try_wait.parity.acquire.cta.shared::cta.b64 P1, [%0], %1, 0x989680;\n\t"
        "@P1 bra.uni WAIT_DONE_%=;\n\t"
        "bra.uni WAIT_LOOP_%=;\n\t"
        "WAIT_DONE_%=:\n\t"
        "}"
        :: "r"(mbar), "r"(parity) : "memory");
}

// ---------------------------------------------------------------------------
// Capacity epilogue (512-thread block; first 256 threads do the scan work).
// Per-group inclusive cumsum of assignments; zero over-capacity one-hots.
// ---------------------------------------------------------------------------
__device__ void capacity_epilogue(int g, float* __restrict__ out) {
    const int tid = threadIdx.x;
    const int lane = tid & 31, wrp = tid >> 5;
    __shared__ int wt[8][NE];

    u64 ids = 0;
    int c[NE], s[NE];
#pragma unroll
    for (int e = 0; e < NE; e++) { c[e] = 0; s[e] = 0; }

    if (tid < 256) {
        ids = ((const u64*)g_expert_id)[g * (NT / 8) + tid];
#pragma unroll
        for (int i = 0; i < 8; i++) {
            int e = (int)((ids >> (8 * i)) & 0xFFULL);
#pragma unroll
            for (int ee = 0; ee < NE; ee++) c[ee] += (e == ee);
        }
#pragma unroll
        for (int e = 0; e < NE; e++) s[e] = c[e];
#pragma unroll
        for (int off = 1; off < 32; off <<= 1) {
#pragma unroll
            for (int e = 0; e < NE; e++) {
                int v = __shfl_up_sync(0xffffffffu, s[e], off);
                if (lane >= off) s[e] += v;
            }
        }
        if (lane == 31) {
#pragma unroll
            for (int e = 0; e < NE; e++) wt[wrp][e] = s[e];
        }
    }
    __syncthreads();
    if (tid < NE) {            // exclusive scan of 8 warp totals
        int run = 0;
#pragma unroll
        for (int w = 0; w < 8; w++) {
            int v = wt[w][tid];
            wt[w][tid] = run;
            run += v;
        }
    }
    __syncthreads();

    if (tid < 256) {
        int base[NE];
#pragma unroll
        for (int e = 0; e < NE; e++) base[e] = (s[e] - c[e]) + wt[wrp][e];

        int run2[NE];
#pragma unroll
        for (int e = 0; e < NE; e++) run2[e] = 0;

        const size_t tok0 = (size_t)g * NT + (size_t)tid * 8;
#pragma unroll
        for (int i = 0; i < 8; i++) {
            int e = (int)((ids >> (8 * i)) & 0xFFULL);
#pragma unroll
            for (int ee = 0; ee < NE; ee++) {
                int inc = (e == ee);
                run2[ee] += inc;
                if (inc && (base[ee] + run2[ee] > CAP))
                    out[(tok0 + i) * NE + ee] = 0.0f;
            }
        }
    }
}

// ---------------------------------------------------------------------------
// Router kernel. x staged through smem by cp.async.bulk (UBLKCP): 64 bulk
// 512B row-copies per stage, mbarrier expect_tx completion, 4-stage pipeline
// (132 KB in flight/SM, zero register/LSU involvement). Compute: lane=token
// (lane, lane+32), warp w owns h-slice [w*8, w*8+8) of each 128-h chunk;
// W reads are smem broadcasts. Per-warp partials reduced via retired stage.
// ---------------------------------------------------------------------------
__global__ __launch_bounds__(THREADS, 1)
void router_kernel(const float* __restrict__ hs,
                   const float* __restrict__ W,
                   const float* __restrict__ bias,
                   float* __restrict__ out) {
    extern __shared__ char smem[];
    u64*   shw      = (u64*)smem;                            // W: 64 KB
    char*  stages   = smem + STAGE_OFF;                      // 4 x 33792
    float* sh_logit = (float*)(smem + MISC_OFF);
    float* sh_bias  = sh_logit + TPBK * 9;
    int*   sh_arg   = (int*)(sh_bias + 8);

    const int tid  = threadIdx.x;
    const int lane = tid & 31, warp = tid >> 5;
    const unsigned smem_u = (unsigned)__cvta_generic_to_shared(smem);
    const unsigned mbar0  = smem_u + MBAR_OFF;

    // init mbarriers (64 producer arrivals per stage round)
    if (tid == 0) {
#pragma unroll
        for (int s = 0; s < NSTAGE; s++) mbar_init(mbar0 + s * 8, 64);
    }
    asm volatile("fence.proxy.async.shared::cta;" ::: "memory");

    // W fill: shwf[h*8 + p*2 + half] = W[2p+half][h]  (broadcast layout)
    {
        float* shwf = (float*)shw;
        const float4* W4 = (const float4*)W;
#pragma unroll
        for (int q = 0; q < 8; q++) {
            int idx4 = tid + q * THREADS;            // 0..4095
            float4 v = W4[idx4];
#pragma unroll
            for (int c = 0; c < 4; c++) {
                int f = idx4 * 4 + c;                // e*2048 + h
                int e = f >> 11, h = f & 2047;
                float val = (c == 0) ? v.x : (c == 1) ? v.y
                          : (c == 2) ? v.z : v.w;
                shwf[h * 8 + (e >> 1) * 2 + (e & 1)] = val;
            }
        }
    }
    if (tid < 8) sh_bias[tid] = bias[tid];
    __syncthreads();           // mbar init + W visible

    const size_t gtok0 = (size_t)blockIdx.x * TPBK;

    // stage issue: threads tid<64 each copy their token's 512B row
    auto issue = [&](int i) {
        if (tid < 64) {
            unsigned mb = mbar0 + (i % NSTAGE) * 8;
            mbar_expect_tx(mb, 512);
            const float* src = hs + (gtok0 + tid) * NH + i * 128;
            unsigned dst = smem_u + STAGE_OFF
                         + (unsigned)((i % NSTAGE) * STAGEB + tid * ROWB);
            bulk_cp(dst, src, 512, mb);
        }
    };

    // prime all 4 stages
    issue(0); issue(1); issue(2); issue(3);

    u64 acc[2][4];
#pragma unroll
    for (int t = 0; t < 2; t++)
#pragma unroll
        for (int p = 0; p < 4; p++) acc[t][p] = 0ULL;

    const int t1 = lane, t2 = lane + 32;

    // compute one 128-h chunk from a stage buffer
    auto compute = [&](int i) {
        const char* st = stages + (i % NSTAGE) * STAGEB;
        const float4* x1 = (const float4*)(st + t1 * ROWB + warp * 32);
        const float4* x2 = (const float4*)(st + t2 * ROWB + warp * 32);
        float4 xa = x1[0], xb = x1[1];               // token t1, h j=0..7
        float4 xc = x2[0], xd = x2[1];               // token t2
        const u64* wb = shw + (size_t)(i * 128 + warp * 8) * 4;
#pragma unroll
        for (int j = 0; j < 8; j++) {
            u64 w0 = wb[j * 4 + 0];
            u64 w1 = wb[j * 4 + 1];
            u64 w2 = wb[j * 4 + 2];
            u64 w3 = wb[j * 4 + 3];
            float xs1 = (j == 0) ? xa.x : (j == 1) ? xa.y : (j == 2) ? xa.z
                      : (j == 3) ? xa.w : (j == 4) ? xb.x : (j == 5) ? xb.y
                      : (j == 6) ? xb.z : xb.w;
            float xs2 = (j == 0) ? xc.x : (j == 1) ? xc.y : (j == 2) ? xc.z
                      : (j == 3) ? xc.w : (j == 4) ? xd.x : (j == 5) ? xd.y
                      : (j == 6) ? xd.z : xd.w;
            u64 d1 = dup2(xs1), d2 = dup2(xs2);
            fma2(acc[0][0], d1, w0);  fma2(acc[1][0], d2, w0);
            fma2(acc[0][1], d1, w1);  fma2(acc[1][1], d2, w1);
            fma2(acc[0][2], d1, w2);  fma2(acc[1][2], d2, w2);
            fma2(acc[0][3], d1, w3);  fma2(acc[1][3], d2, w3);
        }
    };

#pragma unroll 1
    for (int i = 0; i < NITER; i++) {
        mbar_wait(mbar0 + (i % NSTAGE) * 8, (i >> 2) & 1);
        compute(i);
        __syncthreads();       // all consumed slot i%NSTAGE
        if (i + NSTAGE < NITER) issue(i + NSTAGE);   // refill same slot
    }

    // per-warp partial logits -> smem (stage slot 0, fully retired)
    {
        u64* part = (u64*)(stages);
#pragma unroll
        for (int t = 0; t < 2; t++)
#pragma unroll
            for (int p = 0; p < 4; p++)
                part[warp * (TPBK * 4) + (lane + t * 32) * 4 + p] = acc[t][p];
    }
    __syncthreads();

    // reduce 16 warp-partials per (token, expert-pair); 256 threads
    if (tid < TPBK * 4) {
        const u64* part = (const u64*)(stages);
        int t = tid >> 2, p = tid & 3;
        u64 s = part[t * 4 + p];
#pragma unroll
        for (int w = 1; w < 16; w++)
            s = add2(s, part[w * (TPBK * 4) + t * 4 + p]);
        float lo, hi;
        unpack2(s, lo, hi);
        sh_logit[t * 9 + 2 * p]     = lo + sh_bias[2 * p];
        sh_logit[t * 9 + 2 * p + 1] = hi + sh_bias[2 * p + 1];
    }
    __syncthreads();

    // softmax stats + argmax (first-max semantics matches jnp.argmax)
    if (tid < TPBK) {
        const float* l = sh_logit + tid * 9;
        float best = l[0]; int bi = 0;
#pragma unroll
        for (int e = 1; e < NE; e++) {
            float v = l[e];
            if (v > best) { best = v; bi = e; }
        }
        float ssum = 0.f;
#pragma unroll
        for (int e = 0; e < NE; e++) ssum += expf(l[e] - best);
        sh_arg[tid] = bi;
        int gt = blockIdx.x * TPBK + tid;
        out[(size_t)NTOK * NE + gt] = 1.0f / ssum;   // max router prob
        g_expert_id[gt] = (unsigned char)bi;
    }
    __syncthreads();

    // one-hot (pre-capacity) + logits: 512 threads = (64 tokens x 8 experts)
    {
        int t = tid >> 3, e = tid & 7;
        int gt = blockIdx.x * TPBK + t;
        out[(size_t)gt * NE + e] = (e == sh_arg[t]) ? 1.0f : 0.0f;
        out[(size_t)NTOK * NE + NTOK + (size_t)gt * NE + e] = sh_logit[t * 9 + e];
    }

    // ---- fused capacity epilogue: last block of each group runs it ----
    __threadfence();
    __syncthreads();
    __shared__ int s_last;
    if (tid == 0) {
        unsigned int v = atomicAdd(&g_cnt[blockIdx.x / BPG], 1u);
        s_last = ((v & (BPG - 1)) == (BPG - 1));
    }
    __syncthreads();
    if (s_last) {
        __threadfence();   // acquire: see all group blocks' writes
        capacity_epilogue(blockIdx.x / BPG, out);
    }
}

// ---------------------------------------------------------------------------
extern "C" void kernel_launch(void* const* d_in, const int* in_sizes, int n_in,
                              void* d_out, int out_size) {
    const float* hs = (const float*)d_in[0];   // [8, 2048, 2048] f32
    const float* W  = (const float*)d_in[1];   // [8, 2048] f32
    const float* b  = (const float*)d_in[2];   // [8] f32
    float* out = (float*)d_out;

    cudaFuncSetAttribute(router_kernel,
                         cudaFuncAttributeMaxDynamicSharedMemorySize, SMEM_TOTAL);

    router_kernel<<<NBLK, THREADS, SMEM_TOTAL>>>(hs, W, b, out);
}

// round 12
// speedup vs baseline: 1.6352x; 1.6352x over previous
#include <cuda_runtime.h>
#include <math.h>

typedef unsigned long long u64;

#define NG 8
#define NT 2048
#define NH 2048
#define NE 8
#define CAP 320
#define NTOK (NG * NT)        // 16384
#define TPW 8                 // tokens per warp
#define TPBK 64               // tokens per block (8 warps * 8)
#define NBLK (NTOK / TPBK)    // 256 (single wave at 2 CTA/SM)
#define BPG (NBLK / NG)       // 32 blocks per group
#define THREADS 256
#define NITER 16              // H chunks of 128 floats
#define PFD 4                 // prefetch distance (iterations ahead)

// scratch: argmax ids; per-group completion counters.
// g_cnt is tested modulo BPG -> never needs resetting across graph replays.
__device__ unsigned char g_expert_id[NTOK];
__device__ unsigned int  g_cnt[NG];

__device__ __forceinline__ void fma2(u64& acc, u64 a, u64 b) {
    asm("fma.rn.f32x2 %0, %1, %2, %0;" : "+l"(acc) : "l"(a), "l"(b));
}
__device__ __forceinline__ u64 add2(u64 a, u64 b) {
    u64 r; asm("add.rn.f32x2 %0, %1, %2;" : "=l"(r) : "l"(a), "l"(b));
    return r;
}
__device__ __forceinline__ u64 pack2(float lo, float hi) {
    u64 r; asm("mov.b64 %0, {%1, %2};" : "=l"(r) : "f"(lo), "f"(hi));
    return r;
}
__device__ __forceinline__ u64 dup2(float v) { return pack2(v, v); }
__device__ __forceinline__ void unpack2(u64 v, float& lo, float& hi) {
    asm("mov.b64 {%0, %1}, %2;" : "=f"(lo), "=f"(hi) : "l"(v));
}
__device__ __forceinline__ void prefetch_l2(const void* p) {
    asm volatile("prefetch.global.L2 [%0];" :: "l"(p));
}

// ---------------------------------------------------------------------------
// Capacity epilogue: per-group inclusive cumsum of assignments; zero the
// over-capacity one-hot entries. Run by the LAST router block of each group.
// ---------------------------------------------------------------------------
__device__ void capacity_epilogue(int g, float* __restrict__ out) {
    const int tid = threadIdx.x;           // 256
    const int lane = tid & 31, wrp = tid >> 5;

    u64 ids = ((const u64*)g_expert_id)[g * (NT / 8) + tid];

    int c[NE], s[NE];
#pragma unroll
    for (int e = 0; e < NE; e++) c[e] = 0;
#pragma unroll
    for (int i = 0; i < 8; i++) {
        int e = (int)((ids >> (8 * i)) & 0xFFULL);
#pragma unroll
        for (int ee = 0; ee < NE; ee++) c[ee] += (e == ee);
    }
#pragma unroll
    for (int e = 0; e < NE; e++) s[e] = c[e];
#pragma unroll
    for (int off = 1; off < 32; off <<= 1) {
#pragma unroll
        for (int e = 0; e < NE; e++) {
            int v = __shfl_up_sync(0xffffffffu, s[e], off);
            if (lane >= off) s[e] += v;
        }
    }

    __shared__ int wt[8][NE];
    if (lane == 31) {
#pragma unroll
        for (int e = 0; e < NE; e++) wt[wrp][e] = s[e];
    }
    __syncthreads();
    if (tid < NE) {            // exclusive scan of 8 warp totals
        int run = 0;
#pragma unroll
        for (int w = 0; w < 8; w++) {
            int v = wt[w][tid];
            wt[w][tid] = run;
            run += v;
        }
    }
    __syncthreads();

    int base[NE];
#pragma unroll
    for (int e = 0; e < NE; e++) base[e] = (s[e] - c[e]) + wt[wrp][e];

    int run2[NE];
#pragma unroll
    for (int e = 0; e < NE; e++) run2[e] = 0;

    const size_t tok0 = (size_t)g * NT + (size_t)tid * 8;
#pragma unroll
    for (int i = 0; i < 8; i++) {
        int e = (int)((ids >> (8 * i)) & 0xFFULL);
#pragma unroll
        for (int ee = 0; ee < NE; ee++) {
            int inc = (e == ee);
            run2[ee] += inc;
            if (inc && (base[ee] + run2[ee] > CAP))
                out[(tok0 + i) * NE + ee] = 0.0f;
        }
    }
}

// ---------------------------------------------------------------------------
// Router kernel (R8 skeleton + L2 prefetch). warp = 8 tokens, lanes span H
// (coalesced LDG.128). Each iteration: one prefetch.global.L2 per lane pulls
// iteration i+PFD's 4KB warp footprint into L2 (fire-and-forget, no regs),
// so the front-batched 8 LDG.128 hit L2 instead of DRAM. W in smem,
// expert-pair packed, streamed per-j. acc[t][p] = packed (logit[2p],[2p+1]).
// ---------------------------------------------------------------------------
__global__ __launch_bounds__(THREADS, 2)
void router_kernel(const float4* __restrict__ hs4,
                   const float* __restrict__ W,
                   const float* __restrict__ bias,
                   float* __restrict__ out) {
    extern __shared__ char smem[];
    u64*   shw      = (u64*)smem;                       // 8192 u64 = 64 KB
    float* sh_logit = (float*)(shw + NE * NH / 2);      // 64*9
    float* sh_bias  = sh_logit + TPBK * 9;              // 8
    int*   sh_arg   = (int*)(sh_bias + 8);              // 64

    const int tid  = threadIdx.x;
    const int lane = tid & 31, warp = tid >> 5;

    // W permuted for expert-pair packing:
    // word[(i*16 + j*4 + p)*32 + l] = (W[2p][h], W[2p+1][h]),
    //   h = i*128 + l*4 + j  -> per-(i,j) the 4 pair-words are at
    // consecutive-lane u64 addresses (conflict-free LDS.64).
    {
        const float2* W2 = (const float2*)W;
        float* shwf = (float*)shw;
        for (int u = tid; u < NE * NH / 2; u += THREADS) {
            int e = u >> 10;
            int h = (u & 1023) * 2;           // even h; covers (h, h+1)
            float2 w = W2[u];
            int i = h >> 7, l = (h >> 2) & 31, j = h & 3;
            int p = e >> 1, pos = e & 1;
            int w0 = ((i * 16 + j * 4 + p) << 5) + l;
            int w1 = ((i * 16 + (j + 1) * 4 + p) << 5) + l;
            shwf[w0 * 2 + pos] = w.x;
            shwf[w1 * 2 + pos] = w.y;
        }
    }
    if (tid < 8) sh_bias[tid] = bias[tid];
    __syncthreads();

    const int tok0 = blockIdx.x * TPBK + warp * TPW;
    const float4* xp = hs4 + (size_t)tok0 * (NH / 4) + lane;

    // per-lane prefetch address: token (lane>>2), 128B line (lane&3)
    const float* pfbase = (const float*)(hs4 + (size_t)tok0 * (NH / 4))
                        + (size_t)(lane >> 2) * NH + (lane & 3) * 32;

    u64 acc[TPW][4];
#pragma unroll
    for (int t = 0; t < TPW; t++)
#pragma unroll
        for (int p = 0; p < 4; p++) acc[t][p] = 0ULL;

    // warm the pipe: prefetch iterations 0..PFD-1's footprint
#pragma unroll
    for (int q = 0; q < PFD; q++)
        prefetch_l2(pfbase + q * 128);

#pragma unroll 1
    for (int i = 0; i < NITER; i++) {
        // fire-and-forget L2 prefetch for iteration i+PFD (4KB warp footprint)
        if (i + PFD < NITER)
            prefetch_l2(pfbase + (i + PFD) * 128);

        // front-batched: 8 independent LDG.128 (512B coalesced each)
        float4 xv[TPW];
#pragma unroll
        for (int t = 0; t < TPW; t++)
            xv[t] = xp[t * (NH / 4) + i * 32];

#pragma unroll
        for (int j = 0; j < 4; j++) {
            u64 w0 = shw[((i * 16 + j * 4 + 0) << 5) + lane];
            u64 w1 = shw[((i * 16 + j * 4 + 1) << 5) + lane];
            u64 w2 = shw[((i * 16 + j * 4 + 2) << 5) + lane];
            u64 w3 = shw[((i * 16 + j * 4 + 3) << 5) + lane];
#pragma unroll
            for (int t = 0; t < TPW; t++) {
                float xs = (j == 0) ? xv[t].x : (j == 1) ? xv[t].y
                         : (j == 2) ? xv[t].z : xv[t].w;
                u64 xd = dup2(xs);
                fma2(acc[t][0], xd, w0);
                fma2(acc[t][1], xd, w1);
                fma2(acc[t][2], xd, w2);
                fma2(acc[t][3], xd, w3);
            }
        }
    }

    // butterfly-reduce packed (token, expert-pair) accumulators across warp
#pragma unroll
    for (int off = 16; off; off >>= 1) {
#pragma unroll
        for (int t = 0; t < TPW; t++)
#pragma unroll
            for (int p = 0; p < 4; p++)
                acc[t][p] = add2(acc[t][p],
                                 __shfl_xor_sync(0xffffffffu, acc[t][p], off));
    }
    if (lane == 0) {
#pragma unroll
        for (int t = 0; t < TPW; t++)
#pragma unroll
            for (int p = 0; p < 4; p++) {
                float lo, hi;
                unpack2(acc[t][p], lo, hi);
                sh_logit[(warp * TPW + t) * 9 + 2 * p]     = lo + sh_bias[2 * p];
                sh_logit[(warp * TPW + t) * 9 + 2 * p + 1] = hi + sh_bias[2 * p + 1];
            }
    }
    __syncthreads();

    // softmax stats + argmax (first-max semantics matches jnp.argmax)
    if (tid < TPBK) {
        const float* l = sh_logit + tid * 9;
        float best = l[0]; int bi = 0;
#pragma unroll
        for (int e = 1; e < NE; e++) {
            float v = l[e];
            if (v > best) { best = v; bi = e; }
        }
        float s = 0.f;
#pragma unroll
        for (int e = 0; e < NE; e++) s += expf(l[e] - best);
        sh_arg[tid] = bi;
        int gt = blockIdx.x * TPBK + tid;
        out[(size_t)NTOK * NE + gt] = 1.0f / s;      // max router prob
        g_expert_id[gt] = (unsigned char)bi;
    }
    __syncthreads();

    // one-hot (pre-capacity) + logits: 512 elems, 2 per thread
#pragma unroll
    for (int k = 0; k < 2; k++) {
        int idx = tid + k * THREADS;      // 0..511
        int t = idx >> 3, e = idx & 7;
        int gt = blockIdx.x * TPBK + t;
        out[(size_t)gt * NE + e] = (e == sh_arg[t]) ? 1.0f : 0.0f;
        out[(size_t)NTOK * NE + NTOK + (size_t)gt * NE + e] = sh_logit[t * 9 + e];
    }

    // ---- fused capacity epilogue: last block of each group runs it ----
    __threadfence();
    __syncthreads();
    __shared__ int s_last;
    if (tid == 0) {
        unsigned int v = atomicAdd(&g_cnt[blockIdx.x / BPG], 1u);
        s_last = ((v & (BPG - 1)) == (BPG - 1));
    }
    __syncthreads();
    if (s_last) {
        __threadfence();   // acquire: see all group blocks' writes
        capacity_epilogue(blockIdx.x / BPG, out);
    }
}

// ---------------------------------------------------------------------------
extern "C" void kernel_launch(void* const* d_in, const int* in_sizes, int n_in,
                              void* d_out, int out_size) {
    const float4* hs = (const float4*)d_in[0];  // [8, 2048, 2048] f32
    const float* W   = (const float*)d_in[1];   // [8, 2048] f32
    const float* b   = (const float*)d_in[2];   // [8] f32
    float* out = (float*)d_out;

    const int smem = NE * NH / 2 * 8            // W u64 (pair-packed)
                   + TPBK * 9 * 4               // logits
                   + 8 * 4                      // bias
                   + TPBK * 4;                  // argmax
    cudaFuncSetAttribute(router_kernel,
                         cudaFuncAttributeMaxDynamicSharedMemorySize, smem);

    router_kernel<<<NBLK, THREADS, smem>>>(hs, W, b, out);
}